// round 11
// baseline (speedup 1.0000x reference)
#include <cuda_runtime.h>
#include <math_constants.h>

#define SIZE 28
#define TSTEPS 64
#define NTHREADS 224         // 7 fully-autonomous warps; warp w owns columns 4w..4w+3
#define CULL_T 12.5f         // log2 peak threshold: dropped contribution < 2^-12.5

__global__ __launch_bounds__(NTHREADS) void draw_image_kernel(
    const float* __restrict__ x,   // (B, T, 3)
    float* __restrict__ out)       // (B, SIZE, SIZE)
{
    // Separable log2-domain form, u*rc0 pre-folded into w:
    //   s(t, r, k) = w'_t + v_t*rr + u_t*(k/SIZE),  k = 0..3
    //   u = 2*G2*x_t, v = 2*G2*y_t,
    //   w' = log2(si_t) - G2*(x^2+y^2) + u*rc0
    //   hoisted per-pixel: e = -G2*(rr^2 + rc_k^2)
    // out = exp2( max_t s + e )
    __shared__ float4 s_list[7 * TSTEPS];   // per-warp private compacted lists (AoS)

    const int b    = blockIdx.x;
    const int tid  = threadIdx.x;
    const int wid  = tid >> 5;
    const int lane = tid & 31;
    const float* xb = x + (size_t)b * TSTEPS * 3;

    const float G2 = 196.0f * 1.4426950408889634f;  // (SIZE/2)^2 * log2(e)
    const float inv_size = 1.0f / SIZE;
    const float HW = 1.5f * inv_size;               // window half-width (col centers)

    const float rc0 = (float)(wid * 4) * inv_size - 0.5f;
    const float mid = rc0 + HW;

    // Phase 1 (per-warp, no CTA barriers): intensity-aware cull + compaction.
    // Peak of stroke t anywhere in this warp's 4-col window is
    //   si * 2^(-G2*dxe^2), dxe = max(0, |x_t - mid| - HW).
    // Drop iff peak < 2^-CULL_T  <=>  G2*dxe^2 - log2(si) >= CULL_T.
    float4* lst = s_list + wid * TSTEPS;
    int cnt = 0;
    #pragma unroll
    for (int h = 0; h < 2; h++) {
        const int t = lane + 32 * h;
        const float xt = __ldg(xb + 3 * t + 0);
        const float yt = __ldg(xb + 3 * t + 1);
        const float st = __ldg(xb + 3 * t + 2);

        const float ls  = __log2f(st);
        const float dxe = fmaxf(fabsf(xt - mid) - HW, 0.0f);
        const bool keep = fmaf(G2 * dxe, dxe, -ls) < CULL_T;

        const unsigned m = __ballot_sync(0xffffffffu, keep);
        if (keep) {
            const float u = (2.0f * G2) * xt;
            const float v = (2.0f * G2) * yt;
            float w = fmaf(fmaf(xt, xt, yt * yt), -G2, ls);
            w = fmaf(u, rc0, w);                   // fold u*rc0
            const int pos = cnt + __popc(m & ((1u << lane) - 1u));
            lst[pos] = make_float4(u, v, w, 0.0f); // STS.128
        }
        cnt += __popc(m);
    }
    const int n4 = (cnt + 3) & ~3;
    if (lane < n4 - cnt)   // padding can never win: fmaf(0, d, -inf) = -inf (no NaN)
        lst[cnt + lane] = make_float4(0.0f, 0.0f, -CUDART_INF_F, 0.0f);
    __syncwarp();

    // Phase 2: lane = row r; 4 px along columns. Per stroke:
    // one LDS.128 (uniform broadcast, imm offset) + 4 FFMA + 4 FMNMX.
    const float rr = (float)lane * inv_size - 0.5f;
    const float d1 = 1.0f * inv_size;
    const float d2 = 2.0f * inv_size;
    const float d3 = 3.0f * inv_size;

    const float ninf = -CUDART_INF_F;
    float a0 = ninf, a1 = ninf, a2 = ninf, a3 = ninf;

    for (int i = 0; i < n4; i += 4) {
        #pragma unroll
        for (int j = 0; j < 4; j++) {
            const float4 s = lst[i + j];            // LDS.128
            const float hh = fmaf(s.y, rr, s.z);    // v*rr + w'
            a0 = fmaxf(a0, hh);
            a1 = fmaxf(a1, fmaf(s.x, d1, hh));
            a2 = fmaxf(a2, fmaf(s.x, d2, hh));
            a3 = fmaxf(a3, fmaf(s.x, d3, hh));
        }
    }

    // Epilogue: hoisted e = -G2*(rr^2 + rc_k^2), raw EX2, one STG.128.
    if (lane < SIZE) {
        const float rc1 = rc0 + d1, rc2 = rc0 + d2, rc3 = rc0 + d3;
        const float er = -G2 * rr * rr;
        const float e0 = fmaf(-G2 * rc0, rc0, er);
        const float e1 = fmaf(-G2 * rc1, rc1, er);
        const float e2 = fmaf(-G2 * rc2, rc2, er);
        const float e3 = fmaf(-G2 * rc3, rc3, er);

        float o0, o1, o2, o3;
        asm("ex2.approx.ftz.f32 %0, %1;" : "=f"(o0) : "f"(a0 + e0));
        asm("ex2.approx.ftz.f32 %0, %1;" : "=f"(o1) : "f"(a1 + e1));
        asm("ex2.approx.ftz.f32 %0, %1;" : "=f"(o2) : "f"(a2 + e2));
        asm("ex2.approx.ftz.f32 %0, %1;" : "=f"(o3) : "f"(a3 + e3));

        float* outp = out + (size_t)b * SIZE * SIZE + lane * SIZE + wid * 4;
        *(float4*)outp = make_float4(o0, o1, o2, o3);
    }
}

extern "C" void kernel_launch(void* const* d_in, const int* in_sizes, int n_in,
                              void* d_out, int out_size)
{
    const float* x = (const float*)d_in[0];
    float* out = (float*)d_out;

    const int B = in_sizes[0] / (TSTEPS * 3);  // 1024

    draw_image_kernel<<<B, NTHREADS>>>(x, out);
}

// round 12
// speedup vs baseline: 1.0938x; 1.0938x over previous
#include <cuda_runtime.h>
#include <math_constants.h>

#define SIZE 28
#define TSTEPS 64
#define NTHREADS 224         // 7 fully-autonomous warps; warp w owns columns 4w..4w+3
#define CULL_T 10.0f         // log2 peak threshold: dropped contribution < 2^-10

__global__ __launch_bounds__(NTHREADS) void draw_image_kernel(
    const float* __restrict__ x,   // (B, T, 3)
    float* __restrict__ out)       // (B, SIZE, SIZE)
{
    // Separable log2-domain form, u*rc0 pre-folded into w:
    //   s(t, r, k) = w'_t + v_t*rr + u_t*(k/SIZE),  k = 0..3
    //   u = 2*G2*x_t, v = 2*G2*y_t,
    //   w' = log2(si_t) - G2*(x^2+y^2) + u*rc0
    //   hoisted per-pixel: e = -G2*(rr^2 + rc_k^2)
    // out = exp2( max_t s + e )
    __shared__ float4 s_list[7 * TSTEPS];   // per-warp private compacted lists (AoS)

    const int b    = blockIdx.x;
    const int tid  = threadIdx.x;
    const int wid  = tid >> 5;
    const int lane = tid & 31;
    const float* xb = x + (size_t)b * TSTEPS * 3;

    const float G2 = 196.0f * 1.4426950408889634f;  // (SIZE/2)^2 * log2(e)
    const float inv_size = 1.0f / SIZE;
    const float HW = 1.5f * inv_size;               // window half-width (col centers)

    const float rc0 = (float)(wid * 4) * inv_size - 0.5f;
    const float mid = rc0 + HW;

    // Phase 1 (per-warp, no CTA barriers): intensity-aware cull + compaction.
    // Peak of stroke t anywhere in this warp's 4-col window is
    //   si * 2^(-G2*dxe^2), dxe = max(0, |x_t - mid| - HW).
    // Drop iff peak < 2^-CULL_T  <=>  G2*dxe^2 - log2(si) >= CULL_T.
    float4* lst = s_list + wid * TSTEPS;
    int cnt = 0;
    #pragma unroll
    for (int h = 0; h < 2; h++) {
        const int t = lane + 32 * h;
        const float xt = __ldg(xb + 3 * t + 0);
        const float yt = __ldg(xb + 3 * t + 1);
        const float st = __ldg(xb + 3 * t + 2);

        const float ls  = __log2f(st);
        const float dxe = fmaxf(fabsf(xt - mid) - HW, 0.0f);
        const bool keep = fmaf(G2 * dxe, dxe, -ls) < CULL_T;

        const unsigned m = __ballot_sync(0xffffffffu, keep);
        if (keep) {
            const float u = (2.0f * G2) * xt;
            const float v = (2.0f * G2) * yt;
            float w = fmaf(fmaf(xt, xt, yt * yt), -G2, ls);
            w = fmaf(u, rc0, w);                   // fold u*rc0
            const int pos = cnt + __popc(m & ((1u << lane) - 1u));
            lst[pos] = make_float4(u, v, w, 0.0f); // STS.128
        }
        cnt += __popc(m);
    }
    const int n4 = (cnt + 3) & ~3;
    if (lane < n4 - cnt)   // padding can never win: fmaf(0, d, -inf) = -inf (no NaN)
        lst[cnt + lane] = make_float4(0.0f, 0.0f, -CUDART_INF_F, 0.0f);
    __syncwarp();

    // Phase 2: lane = row r; 4 px along columns. Per stroke:
    // one LDS.128 (uniform broadcast, imm offset) + 4 FFMA + 4 FMNMX.
    const float rr = (float)lane * inv_size - 0.5f;
    const float d1 = 1.0f * inv_size;
    const float d2 = 2.0f * inv_size;
    const float d3 = 3.0f * inv_size;

    const float ninf = -CUDART_INF_F;
    float a0 = ninf, a1 = ninf, a2 = ninf, a3 = ninf;

    for (int i = 0; i < n4; i += 4) {
        #pragma unroll
        for (int j = 0; j < 4; j++) {
            const float4 s = lst[i + j];            // LDS.128
            const float hh = fmaf(s.y, rr, s.z);    // v*rr + w'
            a0 = fmaxf(a0, hh);
            a1 = fmaxf(a1, fmaf(s.x, d1, hh));
            a2 = fmaxf(a2, fmaf(s.x, d2, hh));
            a3 = fmaxf(a3, fmaf(s.x, d3, hh));
        }
    }

    // Epilogue: hoisted e = -G2*(rr^2 + rc_k^2), raw EX2, one STG.128.
    if (lane < SIZE) {
        const float rc1 = rc0 + d1, rc2 = rc0 + d2, rc3 = rc0 + d3;
        const float er = -G2 * rr * rr;
        const float e0 = fmaf(-G2 * rc0, rc0, er);
        const float e1 = fmaf(-G2 * rc1, rc1, er);
        const float e2 = fmaf(-G2 * rc2, rc2, er);
        const float e3 = fmaf(-G2 * rc3, rc3, er);

        float o0, o1, o2, o3;
        asm("ex2.approx.ftz.f32 %0, %1;" : "=f"(o0) : "f"(a0 + e0));
        asm("ex2.approx.ftz.f32 %0, %1;" : "=f"(o1) : "f"(a1 + e1));
        asm("ex2.approx.ftz.f32 %0, %1;" : "=f"(o2) : "f"(a2 + e2));
        asm("ex2.approx.ftz.f32 %0, %1;" : "=f"(o3) : "f"(a3 + e3));

        float* outp = out + (size_t)b * SIZE * SIZE + lane * SIZE + wid * 4;
        *(float4*)outp = make_float4(o0, o1, o2, o3);
    }
}

extern "C" void kernel_launch(void* const* d_in, const int* in_sizes, int n_in,
                              void* d_out, int out_size)
{
    const float* x = (const float*)d_in[0];
    float* out = (float*)d_out;

    const int B = in_sizes[0] / (TSTEPS * 3);  // 1024

    draw_image_kernel<<<B, NTHREADS>>>(x, out);
}